// round 12
// baseline (speedup 1.0000x reference)
#include <cuda_runtime.h>
#include <cuda_bf16.h>
#include <cstdint>

// Problem constants
#define B_    32
#define CIN_  128
#define HH_   64
#define WW_   64
#define COUT_ 128
#define NK_   4
#define HID_  32
#define TEMP_ 34.0f

#define NTILES 1024      // 32 samples x 32 row-pairs
#define NCTAS  296       // 2 per SM x 148 SMs, persistent

// ---------------------------------------------------------------------------
// Device scratch
// ---------------------------------------------------------------------------
__device__ float g_ctx [B_ * CIN_];
__device__ float g_att [B_ * NK_];
__device__ float g_aggb[B_ * COUT_];
// Aggregated weights, bf16 hi/lo planes, layout [b][chunk(4)][tap(9)][co(128)][ci(32)]
__device__ __align__(16) __nv_bfloat16 g_wa_hi[(size_t)B_ * 4 * 9 * 128 * 32];
__device__ __align__(16) __nv_bfloat16 g_wa_lo[(size_t)B_ * 4 * 9 * 128 * 32];

// ---------------------------------------------------------------------------
// PTX helpers (family-common: sm_80 mma + cp.async, sm_75 ldmatrix)
// ---------------------------------------------------------------------------
__device__ __forceinline__ void mma_bf16(float* d, const uint32_t* a, const uint32_t* b) {
    asm volatile(
        "mma.sync.aligned.m16n8k16.row.col.f32.bf16.bf16.f32 "
        "{%0,%1,%2,%3}, {%4,%5,%6,%7}, {%8,%9}, {%0,%1,%2,%3};"
        : "+f"(d[0]), "+f"(d[1]), "+f"(d[2]), "+f"(d[3])
        : "r"(a[0]), "r"(a[1]), "r"(a[2]), "r"(a[3]), "r"(b[0]), "r"(b[1]));
}
__device__ __forceinline__ void ldsm_x4(uint32_t& r0, uint32_t& r1,
                                        uint32_t& r2, uint32_t& r3, uint32_t addr) {
    asm volatile("ldmatrix.sync.aligned.m8n8.x4.shared.b16 {%0,%1,%2,%3}, [%4];"
                 : "=r"(r0), "=r"(r1), "=r"(r2), "=r"(r3) : "r"(addr));
}
__device__ __forceinline__ uint32_t smem_u32(const void* p) {
    uint32_t a;
    asm("{ .reg .u64 t; cvta.to.shared.u64 t, %1; cvt.u32.u64 %0, t; }"
        : "=r"(a) : "l"(p));
    return a;
}
__device__ __forceinline__ uint32_t pack_bf16x2(__nv_bfloat16 lo, __nv_bfloat16 hi) {
    return (uint32_t)__bfloat16_as_ushort(lo) | ((uint32_t)__bfloat16_as_ushort(hi) << 16);
}
__device__ __forceinline__ void cp16(uint32_t dst, const void* src) {
    asm volatile("cp.async.cg.shared.global [%0], [%1], 16;"
                 :: "r"(dst), "l"(src) : "memory");
}
__device__ __forceinline__ void cp_commit() {
    asm volatile("cp.async.commit_group;" ::: "memory");
}
__device__ __forceinline__ void cp_wait_all() {
    asm volatile("cp.async.wait_group 0;" ::: "memory");
}

// ---------------------------------------------------------------------------
// Kernel A1: global average pool -> g_ctx
// ---------------------------------------------------------------------------
__global__ void pool_kernel(const float* __restrict__ x)
{
    const int bc = blockIdx.x;
    const float4* p = (const float4*)(x + (size_t)bc * (HH_ * WW_));
    float s = 0.f;
    #pragma unroll
    for (int i = 0; i < 8; ++i) {
        float4 v = p[threadIdx.x + (i << 7)];
        s += (v.x + v.y) + (v.z + v.w);
    }
    #pragma unroll
    for (int o = 16; o > 0; o >>= 1) s += __shfl_down_sync(0xffffffffu, s, o);
    __shared__ float ws[4];
    const int lane = threadIdx.x & 31, wid = threadIdx.x >> 5;
    if (lane == 0) ws[wid] = s;
    __syncthreads();
    if (threadIdx.x == 0)
        g_ctx[bc] = (ws[0] + ws[1] + ws[2] + ws[3]) * (1.0f / (HH_ * WW_));
}

// ---------------------------------------------------------------------------
// Kernel A2: MLP -> softmax -> att + aggregated bias
// ---------------------------------------------------------------------------
__global__ void mlp_kernel(const float* __restrict__ fc1_w,
                           const float* __restrict__ fc2_w,
                           const float* __restrict__ fc2_b,
                           const float* __restrict__ bias)
{
    __shared__ float ctx[CIN_];
    __shared__ float hid[HID_];
    __shared__ float att[NK_];

    const int b   = blockIdx.x;
    const int tid = threadIdx.x;   // 128 threads

    ctx[tid] = g_ctx[b * CIN_ + tid];
    __syncthreads();

    if (tid < HID_) {
        float s = 0.f;
        #pragma unroll 8
        for (int c = 0; c < CIN_; ++c) s += ctx[c] * fc1_w[tid * CIN_ + c];
        hid[tid] = fmaxf(s, 0.f);
    }
    __syncthreads();

    if (tid < NK_) {
        float s = fc2_b[tid];
        #pragma unroll
        for (int i = 0; i < HID_; ++i) s += hid[i] * fc2_w[tid * HID_ + i];
        att[tid] = s * (1.0f / TEMP_);
    }
    __syncthreads();

    if (tid == 0) {
        float m = att[0];
        #pragma unroll
        for (int k = 1; k < NK_; ++k) m = fmaxf(m, att[k]);
        float e[NK_], den = 0.f;
        #pragma unroll
        for (int k = 0; k < NK_; ++k) { e[k] = expf(att[k] - m); den += e[k]; }
        float inv = 1.0f / den;
        #pragma unroll
        for (int k = 0; k < NK_; ++k) {
            att[k] = e[k] * inv;
            g_att[b * NK_ + k] = att[k];
        }
    }
    __syncthreads();

    {
        float s = 0.f;
        #pragma unroll
        for (int k = 0; k < NK_; ++k) s += att[k] * bias[k * COUT_ + tid];
        g_aggb[b * COUT_ + tid] = s;
    }
}

// ---------------------------------------------------------------------------
// Kernel B: aggregate expert weights -> bf16 hi/lo planes.
// Layout [b][chunk(4)][tap(9)][co(128)][ci(32)]: 8KB contiguous per (b,chunk,tap).
// ---------------------------------------------------------------------------
__global__ void aggw_kernel(const float* __restrict__ weight)
{
    const int co = blockIdx.x;
    const int ci = threadIdx.x;
    const int b0 = blockIdx.y * 4;

    float wv[4][9];
    #pragma unroll
    for (int e = 0; e < 4; ++e) {
        const float* p = weight + (((size_t)e * 128 + co) * 128 + ci) * 9;
        #pragma unroll
        for (int kk = 0; kk < 9; ++kk) wv[e][kk] = p[kk];
    }
    const int chunk = ci >> 5, cil = ci & 31;
    #pragma unroll
    for (int bb = 0; bb < 4; ++bb) {
        const int b = b0 + bb;
        const float a0 = g_att[b * 4 + 0], a1 = g_att[b * 4 + 1];
        const float a2 = g_att[b * 4 + 2], a3 = g_att[b * 4 + 3];
        #pragma unroll
        for (int kk = 0; kk < 9; ++kk) {
            float v = a0 * wv[0][kk] + a1 * wv[1][kk]
                    + a2 * wv[2][kk] + a3 * wv[3][kk];
            __nv_bfloat16 hi = __float2bfloat16(v);
            __nv_bfloat16 lo = __float2bfloat16(v - __bfloat162float(hi));
            size_t off = ((((size_t)b * 4 + chunk) * 9 + kk) * 128 + co) * 32 + cil;
            g_wa_hi[off] = hi;
            g_wa_lo[off] = lo;
        }
    }
}

// ---------------------------------------------------------------------------
// Kernel C: persistent implicit-GEMM conv via mma.sync bf16x3.
// Grid = 296 CTAs (2/SM); CTA bid does tiles bid, bid+296, ... (3 or 4 tiles).
// Tile = (sample b, 2 output rows): D[128 co][128 pos], 4 warps, warp 64x64.
// smem rows padded to 80B (20-word stride -> LDSM conflict-free).
// A tiles double-buffered via cp.async, prefetched one tap ahead.
// ---------------------------------------------------------------------------
#define XROW   80                          // bytes per pos-row (32 ci bf16 + pad)
#define SM_XTH  512
#define SM_XTL  (SM_XTH + 4 * 66 * XROW)   // +21120
#define SM_A0   (SM_XTL + 4 * 66 * XROW)   // buf0 hi
#define APLANE  (128 * XROW)               // 10240 per plane
#define ABUF    (2 * APLANE)               // 20480 per buffer (hi+lo)
#define SMEM_SZ (SM_A0 + 2 * ABUF)         // 83712

__global__ void __launch_bounds__(128, 2)
conv_kernel(const float* __restrict__ x, float* __restrict__ out)
{
    extern __shared__ __align__(16) char smem[];
    const uint32_t smb = smem_u32(smem);
    const int tid  = threadIdx.x;
    const int wid  = tid >> 5;
    const int lane = tid & 31;
    const int wm   = wid & 1;        // co half
    const int wn   = wid >> 1;       // output row within pair
    const int g    = lane >> 2, t = lane & 3;

    // zero halo columns (scol 0 and 65), both planes — once, stays zero
    #pragma unroll
    for (int i = 0; i < 2; ++i) {
        const int idx  = tid + i * 128;          // 0..255
        const int plane = idx >> 7;
        const int j    = idx & 127;
        const int ciq  = j & 15;
        const int scol = ((j >> 4) & 1) ? 65 : 0;
        const int srow = j >> 5;
        const uint32_t off = (uint32_t)(srow * 66 + scol) * XROW + ciq * 4;
        *(uint32_t*)(smem + (plane ? SM_XTL : SM_XTH) + off) = 0u;
    }

    // per-thread cp.async A-tile offsets (4 x uint4 per plane)
    uint32_t cpoff[4];
    #pragma unroll
    for (int i = 0; i < 4; ++i) {
        const int idx = tid + i * 128;   // 0..511 uint4
        cpoff[i] = (uint32_t)(idx >> 2) * XROW + (idx & 3) * 16;
    }

    // per-warp ldmatrix base offsets (lane-dependent parts)
    const uint32_t a_lane = (uint32_t)(lane & 15) * XROW + (lane >> 4) * 16;
    const uint32_t b_lane = (uint32_t)(((lane >> 4) << 3) + (lane & 7)) * XROW
                          + ((lane >> 3) & 1) * 16;

    // ---- persistent tile loop: tiles bid, bid+296, ... ----
    #pragma unroll 1
    for (unsigned tile = blockIdx.x; tile < NTILES; tile += NCTAS) {
        const int b  = tile & 31;
        const int h0 = (tile >> 5) * 2;
        const float* xb = x + (size_t)b * CIN_ * HH_ * WW_;
        const size_t wb_b = (size_t)b * 4 * 9 * 4096;

        float acc[4][8][4];
        #pragma unroll
        for (int mt = 0; mt < 4; ++mt)
            #pragma unroll
            for (int nt = 0; nt < 8; ++nt)
                #pragma unroll
                for (int i = 0; i < 4; ++i) acc[mt][nt][i] = 0.f;

        // issue A prefetch for gt=0 into buf0
        #pragma unroll
        for (int i = 0; i < 4; ++i) {
            const int idx = tid + i * 128;
            cp16(smb + SM_A0 + cpoff[i],          (const char*)(g_wa_hi + wb_b) + idx * 16);
            cp16(smb + SM_A0 + APLANE + cpoff[i], (const char*)(g_wa_lo + wb_b) + idx * 16);
        }
        cp_commit();

        #pragma unroll 1
        for (int cc = 0; cc < 4; ++cc) {
            // ---- stage xT chunk: hi/lo bf16, [srow][scol][ci32 pad40] ----
            // (safe vs prior reads: previous tap/tile ended with __syncthreads)
            #pragma unroll
            for (int i = 0; i < 32; ++i) {
                const int idx  = tid + i * 128;
                const int col  = idx & 63;
                const int srow = (idx >> 6) & 3;
                const int ci2  = idx >> 8;          // 0..15
                const int grow = h0 - 1 + srow;
                float v0 = 0.f, v1 = 0.f;
                if ((unsigned)grow < (unsigned)HH_) {
                    const float* p = xb + ((size_t)(cc * 32 + ci2 * 2) * HH_ + grow) * WW_ + col;
                    v0 = p[0];
                    v1 = p[HH_ * WW_];
                }
                const __nv_bfloat16 h0b = __float2bfloat16(v0);
                const __nv_bfloat16 h1b = __float2bfloat16(v1);
                const __nv_bfloat16 l0b = __float2bfloat16(v0 - __bfloat162float(h0b));
                const __nv_bfloat16 l1b = __float2bfloat16(v1 - __bfloat162float(h1b));
                const uint32_t off = (uint32_t)(srow * 66 + col + 1) * XROW + ci2 * 4;
                *(uint32_t*)(smem + SM_XTH + off) = pack_bf16x2(h0b, h1b);
                *(uint32_t*)(smem + SM_XTL + off) = pack_bf16x2(l0b, l1b);
            }
            cp_wait_all();        // A tile for this chunk's tap0 is resident
            __syncthreads();

            #pragma unroll 1
            for (int tap = 0; tap < 9; ++tap) {
                const int gt = cc * 9 + tap;
                const int kh = tap / 3, kw = tap - kh * 3;

                // ---- prefetch A for gt+1 into the other parity buffer ----
                if (gt < 35) {
                    const size_t src = wb_b + (size_t)(gt + 1) * 4096;
                    const uint32_t dst = smb + SM_A0 + (uint32_t)(((gt + 1) & 1) * ABUF);
                    #pragma unroll
                    for (int i = 0; i < 4; ++i) {
                        const int idx = tid + i * 128;
                        cp16(dst + cpoff[i],          (const char*)(g_wa_hi + src) + idx * 16);
                        cp16(dst + APLANE + cpoff[i], (const char*)(g_wa_lo + src) + idx * 16);
                    }
                    cp_commit();
                }

                const uint32_t abase = smb + SM_A0 + (uint32_t)((gt & 1) * ABUF)
                                     + (uint32_t)(wm * 64) * XROW + a_lane;
                // stored index for output col c, tap kw is (c + kw): staging puts
                // input col at index col+1, and input col = c + kw - 1.
                const uint32_t bbase = smb + SM_XTH
                                     + (uint32_t)((wn + kh) * 66 + kw) * XROW + b_lane;

                #pragma unroll
                for (int ks = 0; ks < 2; ++ks) {
                    const uint32_t kso = ks * 32;

                    uint32_t bh[8][2], bl[8][2];
                    #pragma unroll
                    for (int q = 0; q < 4; ++q) {
                        const uint32_t ba = bbase + q * (16 * XROW) + kso;
                        ldsm_x4(bh[2*q][0], bh[2*q][1], bh[2*q+1][0], bh[2*q+1][1], ba);
                        ldsm_x4(bl[2*q][0], bl[2*q][1], bl[2*q+1][0], bl[2*q+1][1],
                                ba + (SM_XTL - SM_XTH));
                    }

                    #pragma unroll
                    for (int mt = 0; mt < 4; ++mt) {
                        const uint32_t aa = abase + (uint32_t)(mt * 16) * XROW + kso;
                        uint32_t ah[4], al[4];
                        ldsm_x4(ah[0], ah[1], ah[2], ah[3], aa);
                        ldsm_x4(al[0], al[1], al[2], al[3], aa + APLANE);
                        #pragma unroll
                        for (int nt = 0; nt < 8; ++nt) mma_bf16(acc[mt][nt], ah, bh[nt]);
                        #pragma unroll
                        for (int nt = 0; nt < 8; ++nt) mma_bf16(acc[mt][nt], ah, bl[nt]);
                        #pragma unroll
                        for (int nt = 0; nt < 8; ++nt) mma_bf16(acc[mt][nt], al, bh[nt]);
                    }
                }

                cp_wait_all();     // next A tile landed (hidden under the MMAs)
                __syncthreads();
            }
        }

        // ---- epilogue: bias (direct LDG) + float2 stores from fragments ----
        #pragma unroll
        for (int mt = 0; mt < 4; ++mt) {
            const int co0 = (wm << 6) + mt * 16 + g;
            const float bv0 = g_aggb[b * COUT_ + co0];
            const float bv1 = g_aggb[b * COUT_ + co0 + 8];
            #pragma unroll
            for (int nt = 0; nt < 8; ++nt) {
                const int ccol = nt * 8 + 2 * t;
                float2 v0 = {acc[mt][nt][0] + bv0, acc[mt][nt][1] + bv0};
                float2 v1 = {acc[mt][nt][2] + bv1, acc[mt][nt][3] + bv1};
                *(float2*)(out + ((size_t)(b * COUT_ + co0    ) * HH_ + h0 + wn) * WW_ + ccol) = v0;
                *(float2*)(out + ((size_t)(b * COUT_ + co0 + 8) * HH_ + h0 + wn) * WW_ + ccol) = v1;
            }
        }
    }
}

// ---------------------------------------------------------------------------
extern "C" void kernel_launch(void* const* d_in, const int* in_sizes, int n_in,
                              void* d_out, int out_size)
{
    const float* x      = (const float*)d_in[0];  // [32,128,64,64]
    const float* fc1_w  = (const float*)d_in[1];  // [32,128]
    const float* fc2_w  = (const float*)d_in[2];  // [4,32]
    const float* fc2_b  = (const float*)d_in[3];  // [4]
    const float* weight = (const float*)d_in[4];  // [4,128,128,3,3]
    const float* bias   = (const float*)d_in[5];  // [4,128]
    float* out = (float*)d_out;                    // [32,128,64,64]

    cudaFuncSetAttribute(conv_kernel,
                         cudaFuncAttributeMaxDynamicSharedMemorySize, SMEM_SZ);

    pool_kernel<<<B_ * CIN_, 128>>>(x);
    mlp_kernel<<<B_, 128>>>(fc1_w, fc2_w, fc2_b, bias);
    aggw_kernel<<<dim3(COUT_, 8), 128>>>(weight);
    conv_kernel<<<NCTAS, 128, SMEM_SZ>>>(x, out);
}